// round 8
// baseline (speedup 1.0000x reference)
#include <cuda_runtime.h>
#include <cuda_bf16.h>
#include <cstdint>

#define B_    4
#define N_    16384
#define C_    64
#define K_    16
#define O_    64
#define RTOT  (B_ * N_)          // 65536 rows
#define TOTSAMP 1048576.0f
#define BN_EPS 1e-5f

__device__ __align__(16) float g_u[RTOT * O_];
__device__ __align__(16) float g_v[RTOT * O_];
__device__ __align__(16) float g_mx[RTOT * O_];
__device__ __align__(16) float g_mn[RTOT * O_];
__device__ float g_sum[O_];
__device__ float g_sq[O_];
// fragment-ordered split weights: [ks(8)][tcol(16)][lane(32)] float2
__device__ __align__(16) float2 g_Bh[8 * 16 * 32];
__device__ __align__(16) float2 g_Bl[8 * 16 * 32];

// ---------------------------------------------------------------------------
// tf32 helpers (baseline sm_80 PTX)
// ---------------------------------------------------------------------------
__device__ __forceinline__ float tf32f(float a) {
    uint32_t u;
    asm("cvt.rna.tf32.f32 %0, %1;" : "=r"(u) : "f"(a));
    return __uint_as_float(u);
}
__device__ __forceinline__ void mma_tf32(float d[4], const uint32_t a[4],
                                         const uint32_t b0, const uint32_t b1) {
    asm volatile(
        "mma.sync.aligned.m16n8k8.row.col.f32.tf32.tf32.f32 "
        "{%0,%1,%2,%3}, {%4,%5,%6,%7}, {%8,%9}, {%0,%1,%2,%3};"
        : "+f"(d[0]), "+f"(d[1]), "+f"(d[2]), "+f"(d[3])
        : "r"(a[0]), "r"(a[1]), "r"(a[2]), "r"(a[3]), "r"(b0), "r"(b1));
}

// ---------------------------------------------------------------------------
// K0: pre-split weights into mma-fragment order + zero stats.
// ---------------------------------------------------------------------------
__global__ void k_prep(const float* __restrict__ w) {
    int i = blockIdx.x * 256 + threadIdx.x;
    if (i < 64) { g_sum[i] = 0.f; g_sq[i] = 0.f; }
    if (i >= 8 * 16 * 32) return;
    int l  = i & 31;
    int t  = (i >> 5) & 15;
    int ks = i >> 9;
    int n = t * 8 + (l >> 2);
    int k = ks * 8 + (l & 3);
    float v0, v1;
    if (n < 64) {
        v0 = w[n * 128 + k]     - w[n * 128 + 64 + k];
        v1 = w[n * 128 + k + 4] - w[n * 128 + 64 + k + 4];
    } else {
        v0 = w[(n - 64) * 128 + 64 + k];
        v1 = w[(n - 64) * 128 + 64 + k + 4];
    }
    float h0 = tf32f(v0), h1 = tf32f(v1);
    g_Bh[i] = make_float2(h0, h1);
    g_Bl[i] = make_float2(tf32f(v0 - h0), tf32f(v1 - h1));
}

// ---------------------------------------------------------------------------
// K1: per-batch GEMM tile (rows rowBase0 + blockIdx.x*64).
// ---------------------------------------------------------------------------
#define XPITCH 68
__global__ __launch_bounds__(256, 3) void k_gemm(const float* __restrict__ x,
                                                 int rowBase0) {
    __shared__ float sX[64][XPITCH];

    int tid = threadIdx.x;
    int lane = tid & 31, wid = tid >> 5;
    int rg = wid & 3, cg = wid >> 2;

    int rowBase = rowBase0 + blockIdx.x * 64;
    const float4* x4 = (const float4*)(x + (size_t)rowBase * 64);
    for (int i = tid; i < 64 * 16; i += 256) {
        int r = i >> 4, c4 = i & 15;
        float4 v = x4[i];
        float* p = &sX[r][c4 * 4];
        p[0] = v.x; p[1] = v.y; p[2] = v.z; p[3] = v.w;
    }
    __syncthreads();

    float acc[8][4] = {};
    int arow = rg * 16 + (lane >> 2);
    int acol = lane & 3;
    const float2* bhBase = g_Bh + cg * 8 * 32 + lane;
    const float2* blBase = g_Bl + cg * 8 * 32 + lane;

#pragma unroll
    for (int ks = 0; ks < 8; ks++) {
        uint32_t ah[4], al[4];
        {
            float x0 = sX[arow][acol + ks * 8];
            float x1 = sX[arow + 8][acol + ks * 8];
            float x2 = sX[arow][acol + 4 + ks * 8];
            float x3 = sX[arow + 8][acol + 4 + ks * 8];
            float h0 = tf32f(x0), h1 = tf32f(x1), h2 = tf32f(x2), h3 = tf32f(x3);
            ah[0] = __float_as_uint(h0); al[0] = __float_as_uint(tf32f(x0 - h0));
            ah[1] = __float_as_uint(h1); al[1] = __float_as_uint(tf32f(x1 - h1));
            ah[2] = __float_as_uint(h2); al[2] = __float_as_uint(tf32f(x2 - h2));
            ah[3] = __float_as_uint(h3); al[3] = __float_as_uint(tf32f(x3 - h3));
        }
        const float2* bh = bhBase + ks * 16 * 32;
        const float2* bl = blBase + ks * 16 * 32;
#pragma unroll
        for (int t = 0; t < 8; t++) {
            float2 h = __ldg(bh + t * 32);
            float2 l = __ldg(bl + t * 32);
            uint32_t b0 = __float_as_uint(h.x), b1 = __float_as_uint(h.y);
            uint32_t c0 = __float_as_uint(l.x), c1 = __float_as_uint(l.y);
            mma_tf32(acc[t], ah, b0, b1);
            mma_tf32(acc[t], ah, c0, c1);
            mma_tf32(acc[t], al, b0, b1);
        }
    }

    float* dst = cg ? g_v : g_u;
    int row = rowBase + rg * 16 + (lane >> 2);
    int col = (lane & 3) * 2;
#pragma unroll
    for (int t = 0; t < 8; t++) {
        *(float2*)(dst + (size_t)row * 64 + t * 8 + col) =
            make_float2(acc[t][0], acc[t][1]);
        *(float2*)(dst + (size_t)(row + 8) * 64 + t * 8 + col) =
            make_float2(acc[t][2], acc[t][3]);
    }
}

// ---------------------------------------------------------------------------
// K2: per-batch gather (points pbase0 .. pbase0 + 16383).
// ---------------------------------------------------------------------------
__global__ __launch_bounds__(256) void k_gather(const int* __restrict__ idx,
                                                int pbase0) {
    int tid  = threadIdx.x;
    int lane = tid & 31;
    int half = lane >> 4;
    int c4   = lane & 15;
    int warpId = blockIdx.x * 8 + (tid >> 5);
    int pbase  = pbase0 + warpId * 16;
    const float4* vb = (const float4*)(g_v + (size_t)pbase0 * O_);  // batch base

    float4 cs1 = {0, 0, 0, 0}, cs2 = {0, 0, 0, 0};

    for (int p = 0; p < 16; ++p) {
        int point = pbase + p;
        const int* ip = idx + (size_t)point * K_;

        float4 u = __ldg((const float4*)(g_u + (size_t)point * O_) + c4);

        float4 mx = make_float4(-3.4e38f, -3.4e38f, -3.4e38f, -3.4e38f);
        float4 mn = make_float4( 3.4e38f,  3.4e38f,  3.4e38f,  3.4e38f);
        float4 s1 = {0, 0, 0, 0}, s2 = {0, 0, 0, 0};
#pragma unroll
        for (int s = 0; s < 8; s++) {
            int j = __ldg(&ip[2 * s + half]);
            float4 v = __ldg(vb + (size_t)j * 16 + c4);
            mx.x = fmaxf(mx.x, v.x); mn.x = fminf(mn.x, v.x); s1.x += v.x; s2.x = fmaf(v.x, v.x, s2.x);
            mx.y = fmaxf(mx.y, v.y); mn.y = fminf(mn.y, v.y); s1.y += v.y; s2.y = fmaf(v.y, v.y, s2.y);
            mx.z = fmaxf(mx.z, v.z); mn.z = fminf(mn.z, v.z); s1.z += v.z; s2.z = fmaf(v.z, v.z, s2.z);
            mx.w = fmaxf(mx.w, v.w); mn.w = fminf(mn.w, v.w); s1.w += v.w; s2.w = fmaf(v.w, v.w, s2.w);
        }
        mx.x = fmaxf(mx.x, __shfl_xor_sync(0xffffffffu, mx.x, 16));
        mx.y = fmaxf(mx.y, __shfl_xor_sync(0xffffffffu, mx.y, 16));
        mx.z = fmaxf(mx.z, __shfl_xor_sync(0xffffffffu, mx.z, 16));
        mx.w = fmaxf(mx.w, __shfl_xor_sync(0xffffffffu, mx.w, 16));
        mn.x = fminf(mn.x, __shfl_xor_sync(0xffffffffu, mn.x, 16));
        mn.y = fminf(mn.y, __shfl_xor_sync(0xffffffffu, mn.y, 16));
        mn.z = fminf(mn.z, __shfl_xor_sync(0xffffffffu, mn.z, 16));
        mn.w = fminf(mn.w, __shfl_xor_sync(0xffffffffu, mn.w, 16));

        if (half == 0) {
            ((float4*)(g_mx + (size_t)point * O_))[c4] =
                make_float4(u.x + mx.x, u.y + mx.y, u.z + mx.z, u.w + mx.w);
            ((float4*)(g_mn + (size_t)point * O_))[c4] =
                make_float4(u.x + mn.x, u.y + mn.y, u.z + mn.z, u.w + mn.w);
        }

        cs1.x += 8.f * u.x + s1.x;  cs2.x += fmaf(8.f * u.x, u.x, fmaf(2.f * u.x, s1.x, s2.x));
        cs1.y += 8.f * u.y + s1.y;  cs2.y += fmaf(8.f * u.y, u.y, fmaf(2.f * u.y, s1.y, s2.y));
        cs1.z += 8.f * u.z + s1.z;  cs2.z += fmaf(8.f * u.z, u.z, fmaf(2.f * u.z, s1.z, s2.z));
        cs1.w += 8.f * u.w + s1.w;  cs2.w += fmaf(8.f * u.w, u.w, fmaf(2.f * u.w, s1.w, s2.w));
    }

    __shared__ float ssum[O_], ssq[O_];
    if (tid < O_) { ssum[tid] = 0.f; ssq[tid] = 0.f; }
    __syncthreads();
    int cb = c4 * 4;
    atomicAdd(&ssum[cb + 0], cs1.x); atomicAdd(&ssq[cb + 0], cs2.x);
    atomicAdd(&ssum[cb + 1], cs1.y); atomicAdd(&ssq[cb + 1], cs2.y);
    atomicAdd(&ssum[cb + 2], cs1.z); atomicAdd(&ssq[cb + 2], cs2.z);
    atomicAdd(&ssum[cb + 3], cs1.w); atomicAdd(&ssq[cb + 3], cs2.w);
    __syncthreads();
    if (tid < O_) {
        atomicAdd(&g_sum[tid], ssum[tid]);
        atomicAdd(&g_sq[tid],  ssq[tid]);
    }
}

// ---------------------------------------------------------------------------
// K3: fused stats + epilogue.
// ---------------------------------------------------------------------------
__global__ __launch_bounds__(256) void k_out(const float* __restrict__ gamma,
                                             const float* __restrict__ beta,
                                             float* __restrict__ out) {
    __shared__ __align__(16) float sc[O_];
    __shared__ __align__(16) float sh[O_];
    __shared__ int negFlag;
    int tid = threadIdx.x;
    if (tid == 0) negFlag = 0;
    __syncthreads();
    if (tid < O_) {
        float inv  = 1.0f / TOTSAMP;
        float mean = g_sum[tid] * inv;
        float var  = g_sq[tid] * inv - mean * mean;
        float s    = rsqrtf(var + BN_EPS) * gamma[tid];
        sc[tid] = s;
        sh[tid] = beta[tid] - mean * s;
        if (s < 0.f) atomicOr(&negFlag, 1);
    }
    __syncthreads();

    size_t i4 = (size_t)blockIdx.x * 256 + tid;
    int o4 = (int)(i4 & 15);
    float4 s4 = ((const float4*)sc)[o4];
    float4 b4 = ((const float4*)sh)[o4];

    float4 m;
    if (!negFlag) {
        m = __ldg((const float4*)g_mx + i4);
    } else {
        float4 a = __ldg((const float4*)g_mx + i4);
        float4 c = __ldg((const float4*)g_mn + i4);
        m.x = (s4.x >= 0.f) ? a.x : c.x;
        m.y = (s4.y >= 0.f) ? a.y : c.y;
        m.z = (s4.z >= 0.f) ? a.z : c.z;
        m.w = (s4.w >= 0.f) ? a.w : c.w;
    }
    float4 r;
    r.x = fmaxf(fmaf(m.x, s4.x, b4.x), 0.f);
    r.y = fmaxf(fmaf(m.y, s4.y, b4.y), 0.f);
    r.z = fmaxf(fmaf(m.z, s4.z, b4.z), 0.f);
    r.w = fmaxf(fmaf(m.w, s4.w, b4.w), 0.f);
    ((float4*)out)[i4] = r;
}

// ---------------------------------------------------------------------------
// Launch: per-batch GEMM on stream G, per-batch gather on stream H chained by
// events, join on the default stream for the epilogue. Streams/events are
// created once (infrastructure handles, identical launch DAG every call).
// ---------------------------------------------------------------------------
static cudaStream_t make_stream() {
    cudaStream_t s; cudaStreamCreateWithFlags(&s, cudaStreamNonBlocking); return s;
}
static cudaEvent_t make_event() {
    cudaEvent_t e; cudaEventCreateWithFlags(&e, cudaEventDisableTiming); return e;
}

extern "C" void kernel_launch(void* const* d_in, const int* in_sizes, int n_in,
                              void* d_out, int out_size) {
    const float* x     = (const float*)d_in[0];
    const int*   idx   = (const int*)  d_in[1];
    const float* w     = (const float*)d_in[2];
    const float* gamma = (const float*)d_in[3];
    const float* beta  = (const float*)d_in[4];
    float* out = (float*)d_out;

    static cudaStream_t sG = make_stream();
    static cudaStream_t sH = make_stream();
    static cudaEvent_t eP  = make_event();
    static cudaEvent_t eG0 = make_event();
    static cudaEvent_t eG1 = make_event();
    static cudaEvent_t eG2 = make_event();
    static cudaEvent_t eG3 = make_event();
    static cudaEvent_t eH  = make_event();
    cudaEvent_t eG[4] = {eG0, eG1, eG2, eG3};

    k_prep<<<16, 256>>>(w);                       // default stream
    cudaEventRecord(eP, 0);
    cudaStreamWaitEvent(sG, eP, 0);
    cudaStreamWaitEvent(sH, eP, 0);

    for (int b = 0; b < 4; b++) {
        k_gemm<<<N_ / 64, 256, 0, sG>>>(x, b * N_);
        cudaEventRecord(eG[b], sG);
        cudaStreamWaitEvent(sH, eG[b], 0);
        k_gather<<<N_ / 128, 256, 0, sH>>>(idx, b * N_);
    }
    cudaEventRecord(eH, sH);
    cudaStreamWaitEvent(0, eH, 0);

    k_out<<<(RTOT * O_ / 4) / 256, 256>>>(gamma, beta, out);
}

// round 9
// speedup vs baseline: 1.9090x; 1.9090x over previous
#include <cuda_runtime.h>
#include <cuda_fp16.h>
#include <cstdint>

#define B_    4
#define N_    16384
#define C_    64
#define K_    16
#define O_    64
#define RTOT  (B_ * N_)          // 65536 rows
#define TOTSAMP 1048576.0f
#define BN_EPS 1e-5f

__device__ __align__(16) float  g_u [RTOT * O_];   // fp32
__device__ __align__(16) __half g_vh[RTOT * O_];   // fp16 (gather operand)
__device__ __align__(16) float  g_mx[RTOT * O_];   // u + max_k v
__device__ __align__(16) float  g_mn[RTOT * O_];   // u + min_k v
__device__ float g_sum[O_];
__device__ float g_sq[O_];
// fragment-ordered split weights: [ks(8)][tcol(16)][lane(32)] float2
__device__ __align__(16) float2 g_Bh[8 * 16 * 32];
__device__ __align__(16) float2 g_Bl[8 * 16 * 32];

// ---------------------------------------------------------------------------
// tf32 helpers (baseline sm_80 PTX)
// ---------------------------------------------------------------------------
__device__ __forceinline__ float tf32f(float a) {
    uint32_t u;
    asm("cvt.rna.tf32.f32 %0, %1;" : "=r"(u) : "f"(a));
    return __uint_as_float(u);
}
__device__ __forceinline__ void mma_tf32(float d[4], const uint32_t a[4],
                                         const uint32_t b0, const uint32_t b1) {
    asm volatile(
        "mma.sync.aligned.m16n8k8.row.col.f32.tf32.tf32.f32 "
        "{%0,%1,%2,%3}, {%4,%5,%6,%7}, {%8,%9}, {%0,%1,%2,%3};"
        : "+f"(d[0]), "+f"(d[1]), "+f"(d[2]), "+f"(d[3])
        : "r"(a[0]), "r"(a[1]), "r"(a[2]), "r"(a[3]), "r"(b0), "r"(b1));
}

// ---------------------------------------------------------------------------
// K0: pre-split weights into mma-fragment order + zero stats.
// ---------------------------------------------------------------------------
__global__ void k_prep(const float* __restrict__ w) {
    int i = blockIdx.x * 256 + threadIdx.x;
    if (i < 64) { g_sum[i] = 0.f; g_sq[i] = 0.f; }
    if (i >= 8 * 16 * 32) return;
    int l  = i & 31;
    int t  = (i >> 5) & 15;
    int ks = i >> 9;
    int n = t * 8 + (l >> 2);
    int k = ks * 8 + (l & 3);
    float v0, v1;
    if (n < 64) {
        v0 = w[n * 128 + k]     - w[n * 128 + 64 + k];
        v1 = w[n * 128 + k + 4] - w[n * 128 + 64 + k + 4];
    } else {
        v0 = w[(n - 64) * 128 + 64 + k];
        v1 = w[(n - 64) * 128 + 64 + k + 4];
    }
    float h0 = tf32f(v0), h1 = tf32f(v1);
    g_Bh[i] = make_float2(h0, h1);
    g_Bl[i] = make_float2(tf32f(v0 - h0), tf32f(v1 - h1));
}

// ---------------------------------------------------------------------------
// K1: [u|v] = x @ [ (W1-W2)^T | W2^T ] — mma.sync tf32, 3xTF32 split.
// CTA: 64 rows x 128 cols, 8 warps; warp (rg=wid&3, cg=wid>>2):
// cg=0 -> u (fp32), cg=1 -> v (fp16 half2).
// ---------------------------------------------------------------------------
#define XPITCH 68
__global__ __launch_bounds__(256, 3) void k_gemm(const float* __restrict__ x) {
    __shared__ float sX[64][XPITCH];

    int tid = threadIdx.x;
    int lane = tid & 31, wid = tid >> 5;
    int rg = wid & 3, cg = wid >> 2;

    int rowBase = blockIdx.x * 64;
    const float4* x4 = (const float4*)(x + (size_t)rowBase * 64);
    for (int i = tid; i < 64 * 16; i += 256) {
        int r = i >> 4, c4 = i & 15;
        float4 v = x4[i];
        float* p = &sX[r][c4 * 4];
        p[0] = v.x; p[1] = v.y; p[2] = v.z; p[3] = v.w;
    }
    __syncthreads();

    float acc[8][4] = {};
    int arow = rg * 16 + (lane >> 2);
    int acol = lane & 3;
    const float2* bhBase = g_Bh + cg * 8 * 32 + lane;
    const float2* blBase = g_Bl + cg * 8 * 32 + lane;

#pragma unroll
    for (int ks = 0; ks < 8; ks++) {
        uint32_t ah[4], al[4];
        {
            float x0 = sX[arow][acol + ks * 8];
            float x1 = sX[arow + 8][acol + ks * 8];
            float x2 = sX[arow][acol + 4 + ks * 8];
            float x3 = sX[arow + 8][acol + 4 + ks * 8];
            float h0 = tf32f(x0), h1 = tf32f(x1), h2 = tf32f(x2), h3 = tf32f(x3);
            ah[0] = __float_as_uint(h0); al[0] = __float_as_uint(tf32f(x0 - h0));
            ah[1] = __float_as_uint(h1); al[1] = __float_as_uint(tf32f(x1 - h1));
            ah[2] = __float_as_uint(h2); al[2] = __float_as_uint(tf32f(x2 - h2));
            ah[3] = __float_as_uint(h3); al[3] = __float_as_uint(tf32f(x3 - h3));
        }
        const float2* bh = bhBase + ks * 16 * 32;
        const float2* bl = blBase + ks * 16 * 32;
#pragma unroll
        for (int t = 0; t < 8; t++) {
            float2 h = __ldg(bh + t * 32);
            float2 l = __ldg(bl + t * 32);
            uint32_t b0 = __float_as_uint(h.x), b1 = __float_as_uint(h.y);
            uint32_t c0 = __float_as_uint(l.x), c1 = __float_as_uint(l.y);
            mma_tf32(acc[t], ah, b0, b1);
            mma_tf32(acc[t], ah, c0, c1);
            mma_tf32(acc[t], al, b0, b1);
        }
    }

    int row = rowBase + rg * 16 + (lane >> 2);
    int col = (lane & 3) * 2;
    if (cg == 0) {
#pragma unroll
        for (int t = 0; t < 8; t++) {
            *(float2*)(g_u + (size_t)row * 64 + t * 8 + col) =
                make_float2(acc[t][0], acc[t][1]);
            *(float2*)(g_u + (size_t)(row + 8) * 64 + t * 8 + col) =
                make_float2(acc[t][2], acc[t][3]);
        }
    } else {
#pragma unroll
        for (int t = 0; t < 8; t++) {
            *(__half2*)(g_vh + (size_t)row * 64 + t * 8 + col) =
                __floats2half2_rn(acc[t][0], acc[t][1]);
            *(__half2*)(g_vh + (size_t)(row + 8) * 64 + t * 8 + col) =
                __floats2half2_rn(acc[t][2], acc[t][3]);
        }
    }
}

// ---------------------------------------------------------------------------
// K2: gather over fp16 v (128 B/row). One warp per 16 points; half-warp per
// k-parity; lane owns 4 channels (one uint2 = 2 half2). shfl_xor(16) merges.
// ---------------------------------------------------------------------------
__global__ __launch_bounds__(256) void k_gather(const int* __restrict__ idx) {
    int tid  = threadIdx.x;
    int lane = tid & 31;
    int half = lane >> 4;
    int c4   = lane & 15;
    int warpId = blockIdx.x * 8 + (tid >> 5);
    int pbase  = warpId * 16;

    float4 cs1 = {0, 0, 0, 0}, cs2 = {0, 0, 0, 0};

    for (int p = 0; p < 16; ++p) {
        int point = pbase + p;
        int b = point >> 14;
        const uint2* vb = (const uint2*)(g_vh + (size_t)b * N_ * O_);  // 8 uint2/row? no: 64 halves = 8 uint2
        const int* ip = idx + (size_t)point * K_;

        float4 u = __ldg((const float4*)(g_u + (size_t)point * O_) + c4);

        float4 mx = make_float4(-3.4e38f, -3.4e38f, -3.4e38f, -3.4e38f);
        float4 mn = make_float4( 3.4e38f,  3.4e38f,  3.4e38f,  3.4e38f);
        float4 s1 = {0, 0, 0, 0}, s2 = {0, 0, 0, 0};
#pragma unroll
        for (int s = 0; s < 8; s++) {
            int j = __ldg(&ip[2 * s + half]);
            // row j = 64 halves = 16 uint2; lane c4 reads uint2 #c4
            uint2 raw = __ldg(vb + (size_t)j * 16 + c4);
            float2 v01 = __half22float2(*(__half2*)&raw.x);
            float2 v23 = __half22float2(*(__half2*)&raw.y);
            mx.x = fmaxf(mx.x, v01.x); mn.x = fminf(mn.x, v01.x); s1.x += v01.x; s2.x = fmaf(v01.x, v01.x, s2.x);
            mx.y = fmaxf(mx.y, v01.y); mn.y = fminf(mn.y, v01.y); s1.y += v01.y; s2.y = fmaf(v01.y, v01.y, s2.y);
            mx.z = fmaxf(mx.z, v23.x); mn.z = fminf(mn.z, v23.x); s1.z += v23.x; s2.z = fmaf(v23.x, v23.x, s2.z);
            mx.w = fmaxf(mx.w, v23.y); mn.w = fminf(mn.w, v23.y); s1.w += v23.y; s2.w = fmaf(v23.y, v23.y, s2.w);
        }
        mx.x = fmaxf(mx.x, __shfl_xor_sync(0xffffffffu, mx.x, 16));
        mx.y = fmaxf(mx.y, __shfl_xor_sync(0xffffffffu, mx.y, 16));
        mx.z = fmaxf(mx.z, __shfl_xor_sync(0xffffffffu, mx.z, 16));
        mx.w = fmaxf(mx.w, __shfl_xor_sync(0xffffffffu, mx.w, 16));
        mn.x = fminf(mn.x, __shfl_xor_sync(0xffffffffu, mn.x, 16));
        mn.y = fminf(mn.y, __shfl_xor_sync(0xffffffffu, mn.y, 16));
        mn.z = fminf(mn.z, __shfl_xor_sync(0xffffffffu, mn.z, 16));
        mn.w = fminf(mn.w, __shfl_xor_sync(0xffffffffu, mn.w, 16));

        if (half == 0) {
            ((float4*)(g_mx + (size_t)point * O_))[c4] =
                make_float4(u.x + mx.x, u.y + mx.y, u.z + mx.z, u.w + mx.w);
            ((float4*)(g_mn + (size_t)point * O_))[c4] =
                make_float4(u.x + mn.x, u.y + mn.y, u.z + mn.z, u.w + mn.w);
        }

        cs1.x += 8.f * u.x + s1.x;  cs2.x += fmaf(8.f * u.x, u.x, fmaf(2.f * u.x, s1.x, s2.x));
        cs1.y += 8.f * u.y + s1.y;  cs2.y += fmaf(8.f * u.y, u.y, fmaf(2.f * u.y, s1.y, s2.y));
        cs1.z += 8.f * u.z + s1.z;  cs2.z += fmaf(8.f * u.z, u.z, fmaf(2.f * u.z, s1.z, s2.z));
        cs1.w += 8.f * u.w + s1.w;  cs2.w += fmaf(8.f * u.w, u.w, fmaf(2.f * u.w, s1.w, s2.w));
    }

    __shared__ float ssum[O_], ssq[O_];
    if (tid < O_) { ssum[tid] = 0.f; ssq[tid] = 0.f; }
    __syncthreads();
    int cb = c4 * 4;
    atomicAdd(&ssum[cb + 0], cs1.x); atomicAdd(&ssq[cb + 0], cs2.x);
    atomicAdd(&ssum[cb + 1], cs1.y); atomicAdd(&ssq[cb + 1], cs2.y);
    atomicAdd(&ssum[cb + 2], cs1.z); atomicAdd(&ssq[cb + 2], cs2.z);
    atomicAdd(&ssum[cb + 3], cs1.w); atomicAdd(&ssq[cb + 3], cs2.w);
    __syncthreads();
    if (tid < O_) {
        atomicAdd(&g_sum[tid], ssum[tid]);
        atomicAdd(&g_sq[tid],  ssq[tid]);
    }
}

// ---------------------------------------------------------------------------
// K3: fused stats + epilogue.
// ---------------------------------------------------------------------------
__global__ __launch_bounds__(256) void k_out(const float* __restrict__ gamma,
                                             const float* __restrict__ beta,
                                             float* __restrict__ out) {
    __shared__ __align__(16) float sc[O_];
    __shared__ __align__(16) float sh[O_];
    __shared__ int negFlag;
    int tid = threadIdx.x;
    if (tid == 0) negFlag = 0;
    __syncthreads();
    if (tid < O_) {
        float inv  = 1.0f / TOTSAMP;
        float mean = g_sum[tid] * inv;
        float var  = g_sq[tid] * inv - mean * mean;
        float s    = rsqrtf(var + BN_EPS) * gamma[tid];
        sc[tid] = s;
        sh[tid] = beta[tid] - mean * s;
        if (s < 0.f) atomicOr(&negFlag, 1);
    }
    __syncthreads();

    size_t i4 = (size_t)blockIdx.x * 256 + tid;
    int o4 = (int)(i4 & 15);
    float4 s4 = ((const float4*)sc)[o4];
    float4 b4 = ((const float4*)sh)[o4];

    float4 m;
    if (!negFlag) {
        m = __ldg((const float4*)g_mx + i4);
    } else {
        float4 a = __ldg((const float4*)g_mx + i4);
        float4 c = __ldg((const float4*)g_mn + i4);
        m.x = (s4.x >= 0.f) ? a.x : c.x;
        m.y = (s4.y >= 0.f) ? a.y : c.y;
        m.z = (s4.z >= 0.f) ? a.z : c.z;
        m.w = (s4.w >= 0.f) ? a.w : c.w;
    }
    float4 r;
    r.x = fmaxf(fmaf(m.x, s4.x, b4.x), 0.f);
    r.y = fmaxf(fmaf(m.y, s4.y, b4.y), 0.f);
    r.z = fmaxf(fmaf(m.z, s4.z, b4.z), 0.f);
    r.w = fmaxf(fmaf(m.w, s4.w, b4.w), 0.f);
    ((float4*)out)[i4] = r;
}

extern "C" void kernel_launch(void* const* d_in, const int* in_sizes, int n_in,
                              void* d_out, int out_size) {
    const float* x     = (const float*)d_in[0];
    const int*   idx   = (const int*)  d_in[1];
    const float* w     = (const float*)d_in[2];
    const float* gamma = (const float*)d_in[3];
    const float* beta  = (const float*)d_in[4];
    float* out = (float*)d_out;

    k_prep  <<<16, 256>>>(w);
    k_gemm  <<<RTOT / 64, 256>>>(x);
    k_gather<<<RTOT / (8 * 16), 256>>>(idx);
    k_out   <<<(RTOT * O_ / 4) / 256, 256>>>(gamma, beta, out);
}